// round 12
// baseline (speedup 1.0000x reference)
#include <cuda_runtime.h>
#include <math.h>
#include <stdint.h>

// Problem constants (fixed-shape problem)
#define BB 8
#define TT 256
#define UU 65
#define VV 1024
#define UM1 64
#define NDIAG 320          // t+u in [0, 319]
#define NROWS (NDIAG + 1)  // +1 padding row so prefetch distance 1 stays in bounds
#define SK 68              // skewed-table row stride in words (even -> float2 aligned)
#define EBIAS 64           // controller set-point: diagonal max held near 2^EBIAS

// Scratch (no cudaMalloc allowed)
__device__ float g_pb[BB * TT * UU];    // p(blank)  [b,t,u]   (probability)
__device__ float g_pl[BB * TT * UM1];   // p(label)  [b,t,u]   (probability)
__device__ float g_cost[BB];
__device__ unsigned int g_done;

// ---------------------------------------------------------------------------
// Kernel 1: per-(b,t,u) row softmax stats over V=1024.
// Stores PROBABILITIES pb = exp(x_blank - lse), pl = exp(x_label - lse).
// One warp per row, 8 float4 loads per lane. 86.9% DRAM — near roofline.
// ---------------------------------------------------------------------------
__global__ __launch_bounds__(256) void rnnt_lse_kernel(
    const float* __restrict__ acts,
    const int* __restrict__ labels)
{
    if (blockIdx.x == 0 && threadIdx.x == 0) g_done = 0u;

    const int warp = (blockIdx.x * blockDim.x + threadIdx.x) >> 5;
    const int lane = threadIdx.x & 31;
    if (warp >= BB * TT * UU) return;

    const int row = warp;                 // row = b*T*U + t*U + u
    const int u   = row % UU;
    const int bt  = row / UU;             // b*T + t
    const int b   = bt / TT;

    const float4* __restrict__ p =
        reinterpret_cast<const float4*>(acts) + (size_t)row * (VV / 4);

    float4 v0 = p[lane];
    float4 v1 = p[lane + 32];
    float4 v2 = p[lane + 64];
    float4 v3 = p[lane + 96];
    float4 v4 = p[lane + 128];
    float4 v5 = p[lane + 160];
    float4 v6 = p[lane + 192];
    float4 v7 = p[lane + 224];

    float m = v0.x;
    m = fmaxf(m, v0.y); m = fmaxf(m, v0.z); m = fmaxf(m, v0.w);
    m = fmaxf(m, v1.x); m = fmaxf(m, v1.y); m = fmaxf(m, v1.z); m = fmaxf(m, v1.w);
    m = fmaxf(m, v2.x); m = fmaxf(m, v2.y); m = fmaxf(m, v2.z); m = fmaxf(m, v2.w);
    m = fmaxf(m, v3.x); m = fmaxf(m, v3.y); m = fmaxf(m, v3.z); m = fmaxf(m, v3.w);
    m = fmaxf(m, v4.x); m = fmaxf(m, v4.y); m = fmaxf(m, v4.z); m = fmaxf(m, v4.w);
    m = fmaxf(m, v5.x); m = fmaxf(m, v5.y); m = fmaxf(m, v5.z); m = fmaxf(m, v5.w);
    m = fmaxf(m, v6.x); m = fmaxf(m, v6.y); m = fmaxf(m, v6.z); m = fmaxf(m, v6.w);
    m = fmaxf(m, v7.x); m = fmaxf(m, v7.y); m = fmaxf(m, v7.z); m = fmaxf(m, v7.w);

    #pragma unroll
    for (int o = 16; o > 0; o >>= 1)
        m = fmaxf(m, __shfl_xor_sync(0xffffffffu, m, o));

    float s = 0.f;
    s += __expf(v0.x - m); s += __expf(v0.y - m); s += __expf(v0.z - m); s += __expf(v0.w - m);
    s += __expf(v1.x - m); s += __expf(v1.y - m); s += __expf(v1.z - m); s += __expf(v1.w - m);
    s += __expf(v2.x - m); s += __expf(v2.y - m); s += __expf(v2.z - m); s += __expf(v2.w - m);
    s += __expf(v3.x - m); s += __expf(v3.y - m); s += __expf(v3.z - m); s += __expf(v3.w - m);
    s += __expf(v4.x - m); s += __expf(v4.y - m); s += __expf(v4.z - m); s += __expf(v4.w - m);
    s += __expf(v5.x - m); s += __expf(v5.y - m); s += __expf(v5.z - m); s += __expf(v5.w - m);
    s += __expf(v6.x - m); s += __expf(v6.y - m); s += __expf(v6.z - m); s += __expf(v6.w - m);
    s += __expf(v7.x - m); s += __expf(v7.y - m); s += __expf(v7.z - m); s += __expf(v7.w - m);

    #pragma unroll
    for (int o = 16; o > 0; o >>= 1)
        s += __shfl_xor_sync(0xffffffffu, s, o);

    if (lane == 0) {
        const float inv_s = 1.0f / s;
        g_pb[row] = __expf(v0.x - m) * inv_s;   // blank prob (element 0 = lane0 v0.x)
        if (u < UM1) {
            const int lab = labels[b * UM1 + u];
            const float xl = __ldg(acts + (size_t)row * VV + lab);
            g_pl[bt * UM1 + u] = __expf(xl - m) * inv_s;
        }
    }
}

// ---------------------------------------------------------------------------
// Kernel 2: prob-domain wavefront, paired lanes + skewed tables +
// MANUAL SOFTWARE PIPELINING. The R10/R11 plateau (~190 cyc/diag) was
// exposed LDS latency: ptxas keeps the 4 table loads adjacent to their
// uses (~100 cyc stalls) + SHFL(32) + REDUX(30). Here each iteration
// PREFETCHES diagonal d+1's operands into registers before computing
// diagonal d, hiding all LDS latency; only the genuinely carried
// shfl+FFMA chain (~50 cyc) remains.
// Lane L owns u=2L (Pe), u=2L+1 (Po); lane 31 also u=64 (P2).
// Skewed tables pbS[t+u][u]=pb[t][u], plS[t+u][u]=pl[t][u-1]; operands of
// diagonal d sit in rows d-1/d; out-of-range entries are zero (boundary
// condition built in). Controller: damped lag-3 gain-1/4 on REDUX max.
// ---------------------------------------------------------------------------
__global__ __launch_bounds__(128) void rnnt_alpha_kernel(
    const int* __restrict__ act_lens,
    const int* __restrict__ label_lens,
    float* __restrict__ out)
{
    extern __shared__ float sm[];
    float* pbS = sm;                    // [NROWS][SK]: pbS[j][u] = pb[j-u][u]
    float* plS = sm + NROWS * SK;       // [NROWS][SK]: plS[j][u] = pl[j-u][u-1]

    const int b   = blockIdx.x;
    const int tid = threadIdx.x;
    const int wrp = tid >> 5;
    const int ln  = tid & 31;

    // Zero-fill both tables incl. padding row (out-of-range == 0 boundary).
    {
        float4* z = reinterpret_cast<float4*>(sm);
        const int n4 = (2 * NROWS * SK) / 4;
        for (int i = tid; i < n4; i += 128)
            z[i] = make_float4(0.f, 0.f, 0.f, 0.f);
    }
    __syncthreads();

    // Fill skewed tables (coalesced gmem reads).
    {
        const float* __restrict__ gb = g_pb + (size_t)b * TT * UU;
        const float* __restrict__ gl = g_pl + (size_t)b * TT * UM1;
        for (int t = wrp; t < TT; t += 4) {
            const float* sb = gb + t * UU;
            pbS[(t + ln) * SK + ln]           = sb[ln];
            pbS[(t + ln + 32) * SK + ln + 32] = sb[ln + 32];
            if (ln == 0) pbS[(t + 64) * SK + 64] = sb[64];
            const float* sl = gl + t * UM1;
            plS[(t + ln + 1) * SK + ln + 1]   = sl[ln];
            plS[(t + ln + 33) * SK + ln + 33] = sl[ln + 32];
        }
    }
    __syncthreads();
    if (wrp != 0) return;   // only warp 0 runs the wavefront

    const int t_tar = act_lens[b] - 1;
    const int u_tar = label_lens[b];
    const int d_tar = t_tar + u_tar;

    const unsigned FULL = 0xffffffffu;

    // Diagonal state. Lane L: Pe = A[2L], Po = A[2L+1]; lane31 also P2 = A[64].
    float Pe = (ln == 0) ? 1.f : 0.f;
    float Po = 0.f;
    float P2 = 0.f;

    int eacc = 0;
    float mh1 = __int_as_float((EBIAS + 127) << 23);   // set-point init
    float mh2 = mh1, mh3 = mh1;

    const float2* pb_row = reinterpret_cast<const float2*>(pbS) + ln;        // row d-1=0
    const float2* pl_row = reinterpret_cast<const float2*>(plS + SK) + ln;   // row d=1
    const float*  pb64p  = pbS + 64;
    const float*  pl64p  = plS + SK + 64;

    // Prologue: preload operands for d=1.
    float2 pbv = *pb_row;
    float2 plv = *pl_row;
    float  pb64 = *pb64p;
    float  pl64 = *pl64p;

    #pragma unroll 4
    for (int d = 1; d <= d_tar; ++d) {
        // PREFETCH diagonal d+1's operands (latency hidden behind compute).
        const float2 pbv_n = pb_row[SK / 2];
        const float2 plv_n = pl_row[SK / 2];
        const float  pb64n = pb64p[SK];
        const float  pl64n = pl64p[SK];

        // Controller (lag-3, gain 1/4) — off the critical path.
        const int e  = ((__float_as_int(mh3) >> 23) & 0xff) - 127;
        const int pe = min(max((e - EBIAS) >> 2, -126), 126);
        const float s = __int_as_float((127 - pe) << 23);

        float po = __shfl_up_sync(FULL, Po, 1);   // A[2L-1]
        if (ln == 0) po = 0.f;

        const float ne = fmaf(Pe, pbv.x, po * plv.x) * s;
        const float no = fmaf(Po, pbv.y, Pe * plv.y) * s;
        const float n2 = fmaf(P2, pb64,  Po * pl64) * s;   // meaningful on lane31

        Pe = ne; Po = no; P2 = n2;
        eacc += pe;

        // Rotate prefetched operands; bump pointers.
        pbv = pbv_n; plv = plv_n; pb64 = pb64n; pl64 = pl64n;
        pb_row += SK / 2; pl_row += SK / 2;
        pb64p  += SK;     pl64p  += SK;

        // Diagonal max via REDUX (non-negative floats: uint order == value order).
        const float lmax = fmaxf(fmaxf(ne, no), n2);
        mh3 = mh2; mh2 = mh1;
        mh1 = __uint_as_float(__reduce_max_sync(FULL, __float_as_uint(lmax)));
    }

    // Extract scaled P at (t_tar, u_tar).
    float cand;
    int src;
    if (u_tar == 64)      { cand = P2; src = 31; }
    else if (u_tar & 1)   { cand = Po; src = u_tar >> 1; }
    else                  { cand = Pe; src = u_tar >> 1; }
    const float res = __shfl_sync(FULL, cand, src);

    if (ln == 0) {
        // alpha = log(res) + eacc*ln2 ; ll = alpha + log(pb[t_tar][u_tar])
        const float alpha = __logf(res) + (float)eacc * 0.69314718056f;
        const float pbt = pbS[d_tar * SK + u_tar];   // pb[t_tar][u_tar]
        g_cost[b] = -(alpha + __logf(pbt));
        __threadfence();
        const unsigned ticket = atomicAdd(&g_done, 1u);
        if (ticket == BB - 1) {
            __threadfence();
            float acc = 0.f;
            #pragma unroll
            for (int i = 0; i < BB; ++i)
                acc += *((volatile float*)&g_cost[i]);
            out[0] = acc * (1.f / (float)BB);
        }
    }
}

extern "C" void kernel_launch(void* const* d_in, const int* in_sizes, int n_in,
                              void* d_out, int out_size)
{
    const float* acts       = (const float*)d_in[0];
    const int*   labels     = (const int*)d_in[1];
    const int*   act_lens   = (const int*)d_in[2];
    const int*   label_lens = (const int*)d_in[3];
    float*       out        = (float*)d_out;

    // Kernel 1: one warp per (b,t,u) row
    {
        const int rows = BB * TT * UU;             // 133120
        const int warpsPerBlock = 8;               // 256 threads
        const int grid = (rows + warpsPerBlock - 1) / warpsPerBlock;
        rnnt_lse_kernel<<<grid, 256>>>(acts, labels);
    }

    // Kernel 2: pipelined paired-lane wavefront (+fused finalize)
    {
        const size_t smem = (size_t)(2 * NROWS * SK) * sizeof(float);  // 174624 B
        cudaFuncSetAttribute(rnnt_alpha_kernel,
                             cudaFuncAttributeMaxDynamicSharedMemorySize,
                             (int)smem);
        rnnt_alpha_kernel<<<BB, 128, smem>>>(act_lens, label_lens, out);
    }
}